// round 10
// baseline (speedup 1.0000x reference)
#include <cuda_runtime.h>
#include <math.h>

// Problem constants (fixed by reference setup_inputs)
#define NB    8        // batches
#define NPIX  65536    // pixels per batch (256*256, C=1)
#define KB    256      // bins; bins[k] == k exactly
#define EPS   1e-10
#define NBX   74       // blocks per batch; 74*8 = 592 = 4*148 -> uniform 4 CTAs/SM
#define PPB   886      // pixels per block (74*886 >= 65536; last block takes 858)
#define NSTATS 16      // joint-stats blocks per batch (bx 0..15)
#define MARG_BX NSTATS // marginal block id (bx 16)
#define NFIN  (NSTATS + 1)   // blocks arriving at bar2 per batch

// Scratch (__device__ globals; zero-initialized at load; every run restores
// the all-zero invariant so CUDA-graph replays start clean).
__device__ float  g_joint[NB * KB * KB];  // per-batch joint weight sums
__device__ float  g_pdf1 [NB * KB];       // marginal weight sums (x1)
__device__ float  g_pdf2 [NB * KB];       // marginal weight sums (x2)
__device__ double g_SJ  [NB];             // sum of joint
__device__ double g_SLJ [NB];             // sum of J * log2(J)
__device__ double g_h1  [NB];             // marginal entropy 1
__device__ double g_h2  [NB];             // marginal entropy 2
__device__ unsigned int g_bar1[NB];       // per-batch barrier (accum->stats)
__device__ unsigned int g_bar2[NB];       // per-batch completion counter

// ---------------------------------------------------------------------------
// Per-pixel sparse KDE: sigma=0.1, bin spacing 1.0 -> nearest bin only.
// Second-nearest weight <= exp(-12.5)=3.7e-6 (expected ~1e-7/pixel): < 1e-6
// relative perturbation. 2 expf + 2 smem atomics + 1 REDG per pixel.
// ---------------------------------------------------------------------------
__device__ __forceinline__ void mi_pix(float a, float c,
                                       float* __restrict__ s1,
                                       float* __restrict__ s2,
                                       float* __restrict__ J) {
    float v1 = a * 255.0f;
    float v2 = c * 255.0f;
    int i1 = __float2int_rn(v1);
    int i2 = __float2int_rn(v2);
    float f1 = v1 - (float)i1;            // f in [-0.5, 0.5]
    float f2 = v2 - (float)i2;
    float w1 = __expf(-50.0f * f1 * f1);
    float w2 = __expf(-50.0f * f2 * f2);
    atomicAdd(&s1[i1], w1);
    atomicAdd(&s2[i2], w2);
    atomicAdd(&J[i1 * KB + i2], w1 * w2);
}

// ---------------------------------------------------------------------------
// Reductions
// ---------------------------------------------------------------------------
__device__ __forceinline__ float warp_reduce_f(float v) {
#pragma unroll
    for (int o = 16; o > 0; o >>= 1)
        v += __shfl_down_sync(0xffffffffu, v, o);
    return v;
}
__device__ __forceinline__ double warp_reduce_d(double v) {
#pragma unroll
    for (int o = 16; o > 0; o >>= 1)
        v += __shfl_down_sync(0xffffffffu, v, o);
    return v;
}
__device__ __forceinline__ double block_reduce_bcast(double v, double* sh8) {
    const int lane = threadIdx.x & 31;
    const int wid  = threadIdx.x >> 5;
    double w = warp_reduce_d(v);
    if (lane == 0) sh8[wid] = w;
    __syncthreads();
    return sh8[0] + sh8[1] + sh8[2] + sh8[3] + sh8[4] + sh8[5] + sh8[6] + sh8[7];
}

__device__ __forceinline__ void jacc(float v, float& s, float& sl) {
    if (v > 0.0f) { s += v; sl += v * __log2f(v); }
}

// ---------------------------------------------------------------------------
// Fused kernel. Grid (NBX, NB) = 592 blocks = EXACTLY 4 CTAs on every SM
// (placement is per-wave uniform; 4 full waves of 148). Uniform occupancy
// kills the deterministic phase-1 straggler that a 512-block grid has
// (68 SMs at 4 CTAs vs 80 at 3). All blocks co-resident
// (__launch_bounds__(256,4)) -> barrier spins cannot deadlock.
//
// Per batch b (74 blocks):
//  Phase 1: 886 pixels/block (last 858), 4 predicated scalar loads per input
//           (128B/warp coalesced, MLP=8).
//  bar1[b]: threadfence + arrive; bx > 16 exits here.
//  Phase 2: bx 0..15: joint stats, 4096 cells each (4 independent float4
//           loads per thread) + zero-restore. bx==16: marginal entropies.
//  Phase 3: last of the 17 (bar2[b]) combines into out[b], resets batch state.
// H12 identity: -sum p*log2(p+EPS) ~= log2(S')*(S/S') - (sum J log2 J)/S',
// S' = S + EPS (deviation < 1e-12 bits).
// ---------------------------------------------------------------------------
__global__ __launch_bounds__(256, 4)
void mi_fused_kernel(const float* __restrict__ x1,
                     const float* __restrict__ x2,
                     float* __restrict__ out) {
    const int b    = blockIdx.y;
    const int bx   = blockIdx.x;
    const int t    = threadIdx.x;
    const int lane = t & 31;
    const int wid  = t >> 5;

    __shared__ float s1[KB];
    __shared__ float s2[KB];
    __shared__ double sh8a[8];
    __shared__ double sh8b[8];
    __shared__ unsigned int lastFlag;

    // ================= Phase 1: accumulation =================
    s1[t] = 0.0f;
    s2[t] = 0.0f;
    __syncthreads();

    float* __restrict__ J = g_joint + (size_t)b * KB * KB;
    {
        const int base = bx * PPB;
        const int cnt  = min(PPB, NPIX - base);   // 858 for bx == 73
        const float* __restrict__ p1 = x1 + (size_t)b * NPIX + base;
        const float* __restrict__ p2 = x2 + (size_t)b * NPIX + base;

        float a[4], c[4];
        bool  m[4];
#pragma unroll
        for (int j = 0; j < 4; ++j) {             // batch loads first: MLP=8
            int i = t + j * 256;
            m[j] = (i < cnt);
            a[j] = m[j] ? p1[i] : 0.0f;
            c[j] = m[j] ? p2[i] : 0.0f;
        }
#pragma unroll
        for (int j = 0; j < 4; ++j)
            if (m[j]) mi_pix(a[j], c[j], s1, s2, J);
    }

    __syncthreads();
    atomicAdd(&g_pdf1[b * KB + t], s1[t]);
    atomicAdd(&g_pdf2[b * KB + t], s2[t]);

    // ================= bar1: arrive (and early-exit) =================
    __threadfence();                      // drain this thread's atomics
    __syncthreads();
    if (bx > MARG_BX) {                   // 57 blocks/batch: arrive and die
        if (t == 0) atomicAdd(&g_bar1[b], 1u);
        return;
    }
    if (t == 0) {
        atomicAdd(&g_bar1[b], 1u);
        while (*(volatile unsigned int*)&g_bar1[b] < NBX)
            __nanosleep(32);
    }
    __syncthreads();

    // ================= Phase 2: statistics =================
    if (bx < NSTATS) {
        // Joint stats: 4096 cells = 4 independent float4 per thread (MLP=4).
        float4* __restrict__ J4 = (float4*)J + bx * 1024 + t;
        float4 v0 = J4[0];
        float4 v1 = J4[256];
        float4 v2 = J4[512];
        float4 v3 = J4[768];

        const float4 z4 = make_float4(0.f, 0.f, 0.f, 0.f);
        J4[0]   = z4;                     // restore zeros for next replay
        J4[256] = z4;
        J4[512] = z4;
        J4[768] = z4;

        float sa = 0.0f, sla = 0.0f, sb = 0.0f, slb = 0.0f;
        jacc(v0.x, sa, sla); jacc(v0.y, sb, slb);
        jacc(v0.z, sa, sla); jacc(v0.w, sb, slb);
        jacc(v1.x, sa, sla); jacc(v1.y, sb, slb);
        jacc(v1.z, sa, sla); jacc(v1.w, sb, slb);
        jacc(v2.x, sa, sla); jacc(v2.y, sb, slb);
        jacc(v2.z, sa, sla); jacc(v2.w, sb, slb);
        jacc(v3.x, sa, sla); jacc(v3.y, sb, slb);
        jacc(v3.z, sa, sla); jacc(v3.w, sb, slb);

        float ws  = warp_reduce_f(sa + sb);
        float wsl = warp_reduce_f(sla + slb);
        if (lane == 0) { sh8a[wid] = (double)ws; sh8b[wid] = (double)wsl; }
        __syncthreads();
        if (t == 0) {
            double bs  = sh8a[0]+sh8a[1]+sh8a[2]+sh8a[3]+sh8a[4]+sh8a[5]+sh8a[6]+sh8a[7];
            double bsl = sh8b[0]+sh8b[1]+sh8b[2]+sh8b[3]+sh8b[4]+sh8b[5]+sh8b[6]+sh8b[7];
            atomicAdd(&g_SJ[b],  bs);
            atomicAdd(&g_SLJ[b], bsl);
        }
    } else {
        // bx == MARG_BX: marginal entropies (double path: h1+h2-h12 cancels).
        const double invN = 1.0 / (double)NPIX;
        double m1 = (double)g_pdf1[b * KB + t] * invN;
        double m2 = (double)g_pdf2[b * KB + t] * invN;
        g_pdf1[b * KB + t] = 0.0f;        // restore zero for replay
        g_pdf2[b * KB + t] = 0.0f;

        double sum1 = block_reduce_bcast(m1, sh8a);
        __syncthreads();
        double sum2 = block_reduce_bcast(m2, sh8a);
        __syncthreads();

        double p1 = m1 / (sum1 + EPS);
        double p2 = m2 / (sum2 + EPS);
        double e1 = p1 * (double)log2f((float)(p1 + EPS));
        double e2 = p2 * (double)log2f((float)(p2 + EPS));

        double h1 = block_reduce_bcast(e1, sh8a);
        __syncthreads();
        double h2 = block_reduce_bcast(e2, sh8a);
        if (t == 0) {
            atomicAdd(&g_h1[b], -h1);
            atomicAdd(&g_h2[b], -h2);
        }
    }

    // ================= Phase 3: per-batch finalize =================
    __syncthreads();
    if (t == 0) {
        __threadfence();                  // order this block's stat atomics
        unsigned int old = atomicAdd(&g_bar2[b], 1u);
        lastFlag = (old == NFIN - 1) ? 1u : 0u;
    }
    __syncthreads();

    if (lastFlag && t == 0) {
        double SJ  = atomicAdd(&g_SJ[b],  0.0);
        double SLJ = atomicAdd(&g_SLJ[b], 0.0);
        double h1  = atomicAdd(&g_h1[b],  0.0);
        double h2  = atomicAdd(&g_h2[b],  0.0);

        double Sp  = SJ + EPS;
        double h12 = (SJ / Sp) * log2(Sp) - SLJ / Sp;
        double mi  = h1 + h2 - h12;
        out[b] = (float)(2.0 * mi / (h1 + h2));   // NORMALIZE

        // reset this batch's state for the next graph replay
        g_SJ[b] = 0.0; g_SLJ[b] = 0.0; g_h1[b] = 0.0; g_h2[b] = 0.0;
        g_bar1[b] = 0u;
        g_bar2[b] = 0u;
    }
}

// ---------------------------------------------------------------------------
// Launch: ONE kernel, 592 blocks = 4 per SM exactly.
// ---------------------------------------------------------------------------
extern "C" void kernel_launch(void* const* d_in, const int* in_sizes, int n_in,
                              void* d_out, int out_size) {
    (void)in_sizes; (void)n_in; (void)out_size;
    const float* x1 = (const float*)d_in[0];
    const float* x2 = (const float*)d_in[1];
    float* out = (float*)d_out;

    dim3 grid(NBX, NB);                   // (74, 8) = 592 blocks
    mi_fused_kernel<<<grid, 256>>>(x1, x2, out);
}